// round 11
// baseline (speedup 1.0000x reference)
#include <cuda_runtime.h>
#include <cstdint>

#define NB     1024
#define NK     5
#define NV     32000
#define ND     128
#define NSPLIT 50

// ---------------- scratch (device globals; no allocation allowed) ----------
__device__ uint32_t g_Vt[ND * (NV / 2)];        // V^T bf16x2 [d][v-word]   8.2 MB
__device__ uint32_t g_Ub[NV * (ND / 2)];        // U   bf16x2 [v][d-word]   8.2 MB
__device__ float    g_part[NSPLIT * NB * ND];   // split-K partials        26.2 MB
__device__ uint32_t g_vi_bf16[NB * (ND / 2)];   // packed vi_embed         256 KB
__device__ float    g_pos[NB];
__device__ float    g_negacc[NB * NK];
__device__ int      g_ctr;

// ---------------- helpers ----------------------------------------------------
static __device__ __forceinline__ uint32_t pack_bf16x2(float lo, float hi) {
    uint32_t r;
    asm("cvt.rn.bf16x2.f32 %0, %1, %2;" : "=r"(r) : "f"(hi), "f"(lo));
    return r;
}
static __device__ __forceinline__ float bf_lo(uint32_t w) { return __uint_as_float(w << 16); }
static __device__ __forceinline__ float bf_hi(uint32_t w) { return __uint_as_float(w & 0xFFFF0000u); }

static __device__ __forceinline__ void mma_bf16(
    float c[4], uint32_t a0, uint32_t a1, uint32_t a2, uint32_t a3,
    uint32_t b0, uint32_t b1)
{
    asm volatile(
        "mma.sync.aligned.m16n8k16.row.col.f32.bf16.bf16.f32 "
        "{%0,%1,%2,%3}, {%4,%5,%6,%7}, {%8,%9}, {%0,%1,%2,%3};"
        : "+f"(c[0]), "+f"(c[1]), "+f"(c[2]), "+f"(c[3])
        : "r"(a0), "r"(a1), "r"(a2), "r"(a3), "r"(b0), "r"(b1));
}

static __device__ __forceinline__ float logsig(float x) {
    float z = -fabsf(x);
    float l = log1pf(__expf(z));
    return (x >= 0.0f) ? -l : (x - l);
}

// ---------------- kernel P: prep (V^T->bf16, U->bf16, zero accumulators) ----
__global__ void __launch_bounds__(256)
prep_kernel(const float* __restrict__ Vm, const float* __restrict__ U)
{
    const int blk = blockIdx.x;
    const int tid = threadIdx.x;

    if (blk < 4000) {
        __shared__ float sm[32][33];
        const int v0 = (blk % 1000) * 32;
        const int d0 = (blk / 1000) * 32;
        #pragma unroll
        for (int p = 0; p < 4; p++) {
            int i = (tid >> 5) + p * 8;
            int j = tid & 31;
            sm[i][j] = Vm[(size_t)(v0 + i) * ND + d0 + j];
        }
        __syncthreads();
        #pragma unroll
        for (int o = 0; o < 2; o++) {
            int row = (tid >> 4) + o * 16;
            int w   = tid & 15;
            uint32_t val = pack_bf16x2(sm[2 * w][row], sm[2 * w + 1][row]);
            g_Vt[(size_t)(d0 + row) * (NV / 2) + (v0 >> 1) + w] = val;
        }
    } else {
        int i0 = (blk - 4000) * 256 + tid;
        #pragma unroll
        for (int p = 0; p < 4; p++) {
            int i = i0 + p * 256000;
            float4 f = ((const float4*)U)[i];
            uint2 o;
            o.x = pack_bf16x2(f.x, f.y);
            o.y = pack_bf16x2(f.z, f.w);
            ((uint2*)g_Ub)[i] = o;
        }
        if (blk == 4000) {
            for (int i = tid; i < NB; i += 256)      g_pos[i] = 0.0f;
            for (int i = tid; i < NB * NK; i += 256) g_negacc[i] = 0.0f;
        }
    }
}

// ---------------- kernel 1: partials of vi @ V  (bf16, split-K, pipelined) --
#define G1S 36
static constexpr int SMEM1 = 2 * 2 * 128 * G1S * 4;   // 73728 B

__global__ void __launch_bounds__(256, 1)
gemm1_kernel(const float* __restrict__ vi)
{
    extern __shared__ uint32_t sm1[];
    const int tid  = threadIdx.x;
    const int wid  = tid >> 5;
    const int lane = tid & 31;
    const int g    = lane >> 2;
    const int tig  = lane & 3;
    const int m0   = blockIdx.x * 128;
    const int wrow = wid * 16;
    const int split = blockIdx.y;
    const size_t kbase = (size_t)split * 640;

    float acc[16][4];
    #pragma unroll
    for (int nt = 0; nt < 16; nt++)
        #pragma unroll
        for (int j = 0; j < 4; j++) acc[nt][j] = 0.0f;

    float4 ra[8];
    uint4  rbv[4];
    const int ar = tid >> 4, ac4 = tid & 15;
    const int brr = tid >> 3, bw4 = tid & 7;

    #define G1_LDG(IT)                                                            \
        do {                                                                      \
            size_t k0 = kbase + (size_t)(IT) * 64;                                \
            _Pragma("unroll")                                                     \
            for (int t = 0; t < 8; t++)                                           \
                ra[t] = *(const float4*)(vi + (size_t)(m0 + ar + t * 16) * NV + k0 + ac4 * 4); \
            _Pragma("unroll")                                                     \
            for (int t = 0; t < 4; t++)                                           \
                rbv[t] = *(const uint4*)(g_Vt + (size_t)(brr + t * 32) * (NV / 2) + (k0 >> 1) + bw4 * 4); \
        } while (0)

    #define G1_STS(P)                                                             \
        do {                                                                      \
            uint32_t* Aw = sm1 + (P) * (2 * 128 * G1S);                           \
            uint32_t* Bw = Aw + 128 * G1S;                                        \
            _Pragma("unroll")                                                     \
            for (int t = 0; t < 8; t++) {                                         \
                uint2 p;                                                          \
                p.x = pack_bf16x2(ra[t].x, ra[t].y);                              \
                p.y = pack_bf16x2(ra[t].z, ra[t].w);                              \
                *(uint2*)(Aw + (ar + t * 16) * G1S + ac4 * 2) = p;                \
            }                                                                     \
            _Pragma("unroll")                                                     \
            for (int t = 0; t < 4; t++)                                           \
                *(uint4*)(Bw + (brr + t * 32) * G1S + bw4 * 4) = rbv[t];          \
        } while (0)

    G1_LDG(0);
    G1_STS(0);
    __syncthreads();

    for (int it = 0; it < 10; it++) {
        if (it + 1 < 10) G1_LDG(it + 1);

        const uint32_t* Aw = sm1 + (it & 1) * (2 * 128 * G1S);
        const uint32_t* Bw = Aw + 128 * G1S;

        #pragma unroll
        for (int ks = 0; ks < 4; ks++) {
            const int kw = ks * 8;
            uint32_t a0 = Aw[(wrow + g)     * G1S + kw + tig];
            uint32_t a1 = Aw[(wrow + g + 8) * G1S + kw + tig];
            uint32_t a2 = Aw[(wrow + g)     * G1S + kw + tig + 4];
            uint32_t a3 = Aw[(wrow + g + 8) * G1S + kw + tig + 4];
            #pragma unroll
            for (int nt = 0; nt < 16; nt++) {
                uint32_t b0 = Bw[(nt * 8 + g) * G1S + kw + tig];
                uint32_t b1 = Bw[(nt * 8 + g) * G1S + kw + tig + 4];
                mma_bf16(acc[nt], a0, a1, a2, a3, b0, b1);
            }
        }

        if (it + 1 < 10) {
            G1_STS(1 - (it & 1));
            __syncthreads();
        }
    }

    float* dst0 = g_part + ((size_t)split * NB + (m0 + wrow + g)) * ND + 2 * tig;
    float* dst1 = dst0 + 8 * ND;
    #pragma unroll
    for (int nt = 0; nt < 16; nt++) {
        *(float2*)(dst0 + nt * 8) = make_float2(acc[nt][0], acc[nt][1]);
        *(float2*)(dst1 + nt * 8) = make_float2(acc[nt][2], acc[nt][3]);
    }
}

// ---------------- kernel R: reduce partials -> packed bf16 vi_embed ---------
__global__ void __launch_bounds__(256)
reduce_kernel()
{
    int e4 = blockIdx.x * 256 + threadIdx.x;
    float4 a = make_float4(0.f, 0.f, 0.f, 0.f);
    #pragma unroll 10
    for (int s = 0; s < NSPLIT; s++) {
        float4 f = *(const float4*)(g_part + (size_t)s * (NB * ND) + (size_t)e4 * 4);
        a.x += f.x; a.y += f.y; a.z += f.z; a.w += f.w;
    }
    uint2 o;
    o.x = pack_bf16x2(a.x, a.y);
    o.y = pack_bf16x2(a.z, a.w);
    ((uint2*)g_vi_bf16)[e4] = o;
}

// ---------------- kernel 2: two-phase — MMA -> smem w (bf16) -> stream ------
// Phase 1: per-warp MMA over its 16-row strip, w packed bf16 into Ws (swizzled).
// Phase 2: per-warp float4 streaming of vo/neg against Ws. Only __syncwarp
// between phases (warp owns its rows end-to-end).
#define BSW 68   // Bs row stride (words): (4g+tig)%32 bijective for frag LDS
#define WSW 72   // Ws row stride (words): phase-distinct banks for LDS.128
static constexpr int SMEM2 = 128 * BSW * 4 + 128 * WSW * 4;   // 71680 B

__global__ void __launch_bounds__(256, 3)
gemm2_kernel(const float* __restrict__ vo, const float* __restrict__ neg,
             float* __restrict__ out)
{
    extern __shared__ uint32_t sm2[];
    uint32_t* Bs = sm2;               // [128][BSW] bf16x2: U tile (row=v)
    uint32_t* Ws = sm2 + 128 * BSW;   // [128][WSW] bf16x2: w tile (row=b)

    const int tid  = threadIdx.x;
    const int wid  = tid >> 5;
    const int lane = tid & 31;
    const int g    = lane >> 2;
    const int tig  = lane & 3;
    const int m0   = blockIdx.x * 128;
    const int v0   = blockIdx.y * 128;
    const int wrow = wid * 16;

    // B tile (bf16x2 pre-packed in gmem)
    #pragma unroll
    for (int t = 0; t < 16; t++) {
        int r = wid + t * 8;
        uint2 w2 = *(const uint2*)(g_Ub + (size_t)(v0 + r) * (ND / 2) + lane * 2);
        *(uint2*)(Bs + r * BSW + lane * 2) = w2;
    }

    // A fragments straight from gmem (L2-resident, 512 KB total)
    uint32_t af[8][4];
    {
        const uint32_t* ap = g_vi_bf16 + (size_t)(m0 + wrow + g) * (ND / 2);
        #pragma unroll
        for (int ks = 0; ks < 8; ks++) {
            af[ks][0] = ap[ks * 8 + tig];
            af[ks][1] = ap[8 * (ND / 2) + ks * 8 + tig];
            af[ks][2] = ap[ks * 8 + tig + 4];
            af[ks][3] = ap[8 * (ND / 2) + ks * 8 + tig + 4];
        }
    }
    __syncthreads();   // Bs ready

    // ---- phase 1: MMA, write w -> Ws (bf16, swizzled blocks of 4 words) ----
    const int rA = wrow + g;          // tile rows this thread produces
    const int rB = rA + 8;
    const int parA = (rA >> 2) & 1;
    const int parB = (rB >> 2) & 1;

    #pragma unroll
    for (int nt = 0; nt < 16; nt++) {
        float a4[4] = {0.0f, 0.0f, 0.0f, 0.0f};
        #pragma unroll
        for (int ks = 0; ks < 8; ks++) {
            uint32_t b0 = Bs[(nt * 8 + g) * BSW + ks * 8 + tig];
            uint32_t b1 = Bs[(nt * 8 + g) * BSW + ks * 8 + tig + 4];
            mma_bf16(a4, af[ks][0], af[ks][1], af[ks][2], af[ks][3], b0, b1);
        }
        const int half = nt >> 3, ntl = nt & 7;
        Ws[rA * WSW + half * 36 + ((ntl ^ parA) << 2) + tig] = pack_bf16x2(a4[0], a4[1]);
        Ws[rB * WSW + half * 36 + ((ntl ^ parB) << 2) + tig] = pack_bf16x2(a4[2], a4[3]);
    }
    __syncwarp();   // warp reads only its own 16 rows below

    // ---- phase 2: stream vo/neg with float4 loads against Ws ----
    const int r   = lane >> 1;          // 0..15 row within strip
    const int h   = lane & 1;           // column half (64 cols)
    const int rt  = wrow + r;
    const int par = (rt >> 2) & 1;
    const int brow = m0 + rt;
    const uint32_t* wp = Ws + rt * WSW + h * 36;
    const float* vp = vo  + (size_t)brow * NV + v0 + h * 64;
    const float* np = neg + (size_t)brow * (NK * NV) + v0 + h * 64;

    float s[6] = {0.f, 0.f, 0.f, 0.f, 0.f, 0.f};

    #pragma unroll
    for (int cb = 0; cb < 8; cb++) {
        uint4 wv = *(const uint4*)(wp + ((cb ^ par) << 2));
        float w0 = bf_lo(wv.x), w1 = bf_hi(wv.x);
        float w2 = bf_lo(wv.y), w3 = bf_hi(wv.y);
        float w4 = bf_lo(wv.z), w5 = bf_hi(wv.z);
        float w6 = bf_lo(wv.w), w7 = bf_hi(wv.w);
        const int off = cb * 8;

        float4 t0 = *(const float4*)(vp + off);
        float4 t1 = *(const float4*)(vp + off + 4);
        s[0] += t0.x * w0 + t0.y * w1 + t0.z * w2 + t0.w * w3
              + t1.x * w4 + t1.y * w5 + t1.z * w6 + t1.w * w7;

        #pragma unroll
        for (int k = 0; k < NK; k++) {
            float4 u0 = *(const float4*)(np + (size_t)k * NV + off);
            float4 u1 = *(const float4*)(np + (size_t)k * NV + off + 4);
            s[k + 1] += u0.x * w0 + u0.y * w1 + u0.z * w2 + u0.w * w3
                      + u1.x * w4 + u1.y * w5 + u1.z * w6 + u1.w * w7;
        }
    }

    // combine the two column halves (lane pairs), then atomics
    #pragma unroll
    for (int i = 0; i < 6; i++)
        s[i] += __shfl_xor_sync(0xFFFFFFFFu, s[i], 1);
    if (h == 0) {
        atomicAdd(&g_pos[brow], s[0]);
        #pragma unroll
        for (int k = 0; k < NK; k++)
            atomicAdd(&g_negacc[brow * NK + k], s[k + 1]);
    }

    // ---- last-CTA finalize ----
    __syncthreads();
    __shared__ int is_last;
    if (tid == 0) {
        __threadfence();
        int old = atomicAdd(&g_ctr, 1);
        is_last = (old == (int)(gridDim.x * gridDim.y) - 1) ? 1 : 0;
    }
    __syncthreads();
    if (is_last) {
        __threadfence();
        float v = 0.0f;
        #pragma unroll
        for (int j = 0; j < 4; j++) {
            int b = tid * 4 + j;
            float l = logsig(__ldcg(&g_pos[b]));
            #pragma unroll
            for (int k = 0; k < NK; k++)
                l += logsig(-__ldcg(&g_negacc[b * NK + k]));
            v += -l;
        }
        #pragma unroll
        for (int o = 16; o > 0; o >>= 1) v += __shfl_xor_sync(0xFFFFFFFFu, v, o);
        __shared__ float red[8];
        if (lane == 0) red[wid] = v;
        __syncthreads();
        if (tid == 0) {
            float sum = 0.0f;
            #pragma unroll
            for (int i = 0; i < 8; i++) sum += red[i];
            out[0] = sum * (1.0f / (float)NB);
            g_ctr = 0;
        }
    }
}

// ---------------- launch -----------------------------------------------------
extern "C" void kernel_launch(void* const* d_in, const int* in_sizes, int n_in,
                              void* d_out, int out_size)
{
    const float* vi  = (const float*)d_in[0];
    const float* vo  = (const float*)d_in[1];
    const float* neg = (const float*)d_in[2];
    const float* Vm  = (const float*)d_in[3];
    const float* U   = (const float*)d_in[4];
    float* out = (float*)d_out;

    cudaFuncSetAttribute(gemm1_kernel, cudaFuncAttributeMaxDynamicSharedMemorySize, SMEM1);
    cudaFuncSetAttribute(gemm2_kernel, cudaFuncAttributeMaxDynamicSharedMemorySize, SMEM2);

    prep_kernel<<<5000, 256>>>(Vm, U);
    gemm1_kernel<<<dim3(8, NSPLIT), 256, SMEM1>>>(vi);
    reduce_kernel<<<128, 256>>>();
    gemm2_kernel<<<dim3(8, 250), 256, SMEM2>>>(vo, neg, out);
}

// round 12
// speedup vs baseline: 2.1622x; 2.1622x over previous
#include <cuda_runtime.h>
#include <cstdint>

#define NB     1024
#define NK     5
#define NV     32000
#define ND     128
#define NSPLIT 50

// ---------------- scratch (device globals; no allocation allowed) ----------
__device__ uint32_t g_Vt[ND * (NV / 2)];        // V^T bf16x2 [d][v-word]   8.2 MB
__device__ uint32_t g_Ub[NV * (ND / 2)];        // U   bf16x2 [v][d-word]   8.2 MB
__device__ float    g_part[NSPLIT * NB * ND];   // split-K partials        26.2 MB
__device__ uint32_t g_vi_bf16[NB * (ND / 2)];   // packed vi_embed         256 KB
__device__ float    g_pos[NB];
__device__ float    g_negacc[NB * NK];
__device__ int      g_ctr;

// ---------------- helpers ----------------------------------------------------
static __device__ __forceinline__ uint32_t pack_bf16x2(float lo, float hi) {
    uint32_t r;
    asm("cvt.rn.bf16x2.f32 %0, %1, %2;" : "=r"(r) : "f"(hi), "f"(lo));
    return r;
}
static __device__ __forceinline__ float bf_lo(uint32_t w) { return __uint_as_float(w << 16); }
static __device__ __forceinline__ float bf_hi(uint32_t w) { return __uint_as_float(w & 0xFFFF0000u); }

static __device__ __forceinline__ void mma_bf16(
    float c[4], uint32_t a0, uint32_t a1, uint32_t a2, uint32_t a3,
    uint32_t b0, uint32_t b1)
{
    asm volatile(
        "mma.sync.aligned.m16n8k16.row.col.f32.bf16.bf16.f32 "
        "{%0,%1,%2,%3}, {%4,%5,%6,%7}, {%8,%9}, {%0,%1,%2,%3};"
        : "+f"(c[0]), "+f"(c[1]), "+f"(c[2]), "+f"(c[3])
        : "r"(a0), "r"(a1), "r"(a2), "r"(a3), "r"(b0), "r"(b1));
}

static __device__ __forceinline__ float logsig(float x) {
    float z = -fabsf(x);
    float l = log1pf(__expf(z));
    return (x >= 0.0f) ? -l : (x - l);
}

static __device__ __forceinline__ float warp_sum(float v) {
    #pragma unroll
    for (int o = 16; o > 0; o >>= 1) v += __shfl_xor_sync(0xFFFFFFFFu, v, o);
    return v;
}

// ---------------- kernel P: prep (V^T->bf16, U->bf16, zero accumulators) ----
__global__ void __launch_bounds__(256)
prep_kernel(const float* __restrict__ Vm, const float* __restrict__ U)
{
    const int blk = blockIdx.x;
    const int tid = threadIdx.x;

    if (blk < 4000) {
        __shared__ float sm[32][33];
        const int v0 = (blk % 1000) * 32;
        const int d0 = (blk / 1000) * 32;
        #pragma unroll
        for (int p = 0; p < 4; p++) {
            int i = (tid >> 5) + p * 8;
            int j = tid & 31;
            sm[i][j] = Vm[(size_t)(v0 + i) * ND + d0 + j];
        }
        __syncthreads();
        #pragma unroll
        for (int o = 0; o < 2; o++) {
            int row = (tid >> 4) + o * 16;
            int w   = tid & 15;
            uint32_t val = pack_bf16x2(sm[2 * w][row], sm[2 * w + 1][row]);
            g_Vt[(size_t)(d0 + row) * (NV / 2) + (v0 >> 1) + w] = val;
        }
    } else {
        int i0 = (blk - 4000) * 256 + tid;
        #pragma unroll
        for (int p = 0; p < 4; p++) {
            int i = i0 + p * 256000;
            float4 f = ((const float4*)U)[i];
            uint2 o;
            o.x = pack_bf16x2(f.x, f.y);
            o.y = pack_bf16x2(f.z, f.w);
            ((uint2*)g_Ub)[i] = o;
        }
        if (blk == 4000) {
            for (int i = tid; i < NB; i += 256)      g_pos[i] = 0.0f;
            for (int i = tid; i < NB * NK; i += 256) g_negacc[i] = 0.0f;
        }
    }
}

// ---------------- kernel 1: partials of vi @ V  (bf16, split-K, pipelined) --
#define G1S 36
static constexpr int SMEM1 = 2 * 2 * 128 * G1S * 4;   // 73728 B

__global__ void __launch_bounds__(256, 1)
gemm1_kernel(const float* __restrict__ vi)
{
    extern __shared__ uint32_t sm1[];
    const int tid  = threadIdx.x;
    const int wid  = tid >> 5;
    const int lane = tid & 31;
    const int g    = lane >> 2;
    const int tig  = lane & 3;
    const int m0   = blockIdx.x * 128;
    const int wrow = wid * 16;
    const int split = blockIdx.y;
    const size_t kbase = (size_t)split * 640;

    float acc[16][4];
    #pragma unroll
    for (int nt = 0; nt < 16; nt++)
        #pragma unroll
        for (int j = 0; j < 4; j++) acc[nt][j] = 0.0f;

    float4 ra[8];
    uint4  rbv[4];
    const int ar = tid >> 4, ac4 = tid & 15;
    const int brr = tid >> 3, bw4 = tid & 7;

    #define G1_LDG(IT)                                                            \
        do {                                                                      \
            size_t k0 = kbase + (size_t)(IT) * 64;                                \
            _Pragma("unroll")                                                     \
            for (int t = 0; t < 8; t++)                                           \
                ra[t] = *(const float4*)(vi + (size_t)(m0 + ar + t * 16) * NV + k0 + ac4 * 4); \
            _Pragma("unroll")                                                     \
            for (int t = 0; t < 4; t++)                                           \
                rbv[t] = *(const uint4*)(g_Vt + (size_t)(brr + t * 32) * (NV / 2) + (k0 >> 1) + bw4 * 4); \
        } while (0)

    #define G1_STS(P)                                                             \
        do {                                                                      \
            uint32_t* Aw = sm1 + (P) * (2 * 128 * G1S);                           \
            uint32_t* Bw = Aw + 128 * G1S;                                        \
            _Pragma("unroll")                                                     \
            for (int t = 0; t < 8; t++) {                                         \
                uint2 p;                                                          \
                p.x = pack_bf16x2(ra[t].x, ra[t].y);                              \
                p.y = pack_bf16x2(ra[t].z, ra[t].w);                              \
                *(uint2*)(Aw + (ar + t * 16) * G1S + ac4 * 2) = p;                \
            }                                                                     \
            _Pragma("unroll")                                                     \
            for (int t = 0; t < 4; t++)                                           \
                *(uint4*)(Bw + (brr + t * 32) * G1S + bw4 * 4) = rbv[t];          \
        } while (0)

    G1_LDG(0);
    G1_STS(0);
    __syncthreads();

    for (int it = 0; it < 10; it++) {
        if (it + 1 < 10) G1_LDG(it + 1);

        const uint32_t* Aw = sm1 + (it & 1) * (2 * 128 * G1S);
        const uint32_t* Bw = Aw + 128 * G1S;

        #pragma unroll
        for (int ks = 0; ks < 4; ks++) {
            const int kw = ks * 8;
            uint32_t a0 = Aw[(wrow + g)     * G1S + kw + tig];
            uint32_t a1 = Aw[(wrow + g + 8) * G1S + kw + tig];
            uint32_t a2 = Aw[(wrow + g)     * G1S + kw + tig + 4];
            uint32_t a3 = Aw[(wrow + g + 8) * G1S + kw + tig + 4];
            #pragma unroll
            for (int nt = 0; nt < 16; nt++) {
                uint32_t b0 = Bw[(nt * 8 + g) * G1S + kw + tig];
                uint32_t b1 = Bw[(nt * 8 + g) * G1S + kw + tig + 4];
                mma_bf16(acc[nt], a0, a1, a2, a3, b0, b1);
            }
        }

        if (it + 1 < 10) {
            G1_STS(1 - (it & 1));
            __syncthreads();
        }
    }

    float* dst0 = g_part + ((size_t)split * NB + (m0 + wrow + g)) * ND + 2 * tig;
    float* dst1 = dst0 + 8 * ND;
    #pragma unroll
    for (int nt = 0; nt < 16; nt++) {
        *(float2*)(dst0 + nt * 8) = make_float2(acc[nt][0], acc[nt][1]);
        *(float2*)(dst1 + nt * 8) = make_float2(acc[nt][2], acc[nt][3]);
    }
}

// ---------------- kernel R: reduce partials -> packed bf16 vi_embed ---------
__global__ void __launch_bounds__(256)
reduce_kernel()
{
    int e4 = blockIdx.x * 256 + threadIdx.x;
    float4 a = make_float4(0.f, 0.f, 0.f, 0.f);
    #pragma unroll 10
    for (int s = 0; s < NSPLIT; s++) {
        float4 f = *(const float4*)(g_part + (size_t)s * (NB * ND) + (size_t)e4 * 4);
        a.x += f.x; a.y += f.y; a.z += f.z; a.w += f.w;
    }
    uint2 o;
    o.x = pack_bf16x2(a.x, a.y);
    o.y = pack_bf16x2(a.z, a.w);
    ((uint2*)g_vi_bf16)[e4] = o;
}

// ---------------- kernel 2: two-phase — MMA -> smem w (bf16) -> stream ------
// Phase 1: per-warp MMA over its 16-row strip; w tile packed bf16 into Ws.
// Phase 2: warp-COOPERATIVE streaming — all 32 lanes read one row's 128
// consecutive floats per LDG (512B, nL=4 minimum), 6 arrays per row
// independent + next-row prefetch for MLP; shfl-reduce per (row, array).
#define BSW 68   // Bs row stride (words)
#define WSW 66   // Ws row stride (words): plain layout, read side conflict-free
static constexpr int SMEM2 = 128 * BSW * 4 + 128 * WSW * 4;   // 68608 B

__global__ void __launch_bounds__(256, 3)
gemm2_kernel(const float* __restrict__ vo, const float* __restrict__ neg,
             float* __restrict__ out)
{
    extern __shared__ uint32_t sm2[];
    uint32_t* Bs = sm2;               // [128][BSW] bf16x2: U tile (row=v)
    uint32_t* Ws = sm2 + 128 * BSW;   // [128][WSW] bf16x2: w tile (row=b)

    const int tid  = threadIdx.x;
    const int wid  = tid >> 5;
    const int lane = tid & 31;
    const int g    = lane >> 2;
    const int tig  = lane & 3;
    const int m0   = blockIdx.x * 128;
    const int v0   = blockIdx.y * 128;
    const int wrow = wid * 16;

    // B tile (bf16x2 pre-packed in gmem)
    #pragma unroll
    for (int t = 0; t < 16; t++) {
        int r = wid + t * 8;
        uint2 w2 = *(const uint2*)(g_Ub + (size_t)(v0 + r) * (ND / 2) + lane * 2);
        *(uint2*)(Bs + r * BSW + lane * 2) = w2;
    }

    // A fragments straight from gmem (L2-resident, 512 KB total)
    uint32_t af[8][4];
    {
        const uint32_t* ap = g_vi_bf16 + (size_t)(m0 + wrow + g) * (ND / 2);
        #pragma unroll
        for (int ks = 0; ks < 8; ks++) {
            af[ks][0] = ap[ks * 8 + tig];
            af[ks][1] = ap[8 * (ND / 2) + ks * 8 + tig];
            af[ks][2] = ap[ks * 8 + tig + 4];
            af[ks][3] = ap[8 * (ND / 2) + ks * 8 + tig + 4];
        }
    }
    __syncthreads();   // Bs ready

    // ---- phase 1: MMA, write w -> Ws (plain layout; word c = col-pair c) ----
    const int rA = wrow + g;
    const int rB = rA + 8;
    #pragma unroll
    for (int nt = 0; nt < 16; nt++) {
        float a4[4] = {0.0f, 0.0f, 0.0f, 0.0f};
        #pragma unroll
        for (int ks = 0; ks < 8; ks++) {
            uint32_t b0 = Bs[(nt * 8 + g) * BSW + ks * 8 + tig];
            uint32_t b1 = Bs[(nt * 8 + g) * BSW + ks * 8 + tig + 4];
            mma_bf16(a4, af[ks][0], af[ks][1], af[ks][2], af[ks][3], b0, b1);
        }
        Ws[rA * WSW + nt * 4 + tig] = pack_bf16x2(a4[0], a4[1]);
        Ws[rB * WSW + nt * 4 + tig] = pack_bf16x2(a4[2], a4[3]);
    }
    __syncwarp();   // warp reads only its own 16 rows below

    // ---- phase 2: warp-cooperative streaming (one row = one coalesced LDG) --
    // lane covers cols 4*lane .. 4*lane+3 of every row.
    const float* vbase = vo  + (size_t)m0 * NV + v0 + lane * 4;
    const float* nbase = neg + (size_t)m0 * (NK * NV) + v0 + lane * 4;

    // prime row 0
    uint2  wv_c = *(const uint2*)(Ws + (wrow + 0) * WSW + lane * 2);
    float4 tv_c = *(const float4*)(vbase + (size_t)(wrow + 0) * NV);
    float4 tn_c[NK];
    #pragma unroll
    for (int k = 0; k < NK; k++)
        tn_c[k] = *(const float4*)(nbase + (size_t)(wrow + 0) * (NK * NV) + (size_t)k * NV);

    #pragma unroll
    for (int r = 0; r < 16; r++) {
        // prefetch next row (independent of this row's compute)
        uint2 wv_n; float4 tv_n, tn_n[NK];
        if (r < 15) {
            const int rn = wrow + r + 1;
            wv_n = *(const uint2*)(Ws + rn * WSW + lane * 2);
            tv_n = *(const float4*)(vbase + (size_t)rn * NV);
            #pragma unroll
            for (int k = 0; k < NK; k++)
                tn_n[k] = *(const float4*)(nbase + (size_t)rn * (NK * NV) + (size_t)k * NV);
        }

        const float w0 = bf_lo(wv_c.x), w1 = bf_hi(wv_c.x);
        const float w2 = bf_lo(wv_c.y), w3 = bf_hi(wv_c.y);
        const int brow = m0 + wrow + r;

        float sv = tv_c.x * w0 + tv_c.y * w1 + tv_c.z * w2 + tv_c.w * w3;
        sv = warp_sum(sv);
        if (lane == 0) atomicAdd(&g_pos[brow], sv);

        #pragma unroll
        for (int k = 0; k < NK; k++) {
            float sn = tn_c[k].x * w0 + tn_c[k].y * w1 + tn_c[k].z * w2 + tn_c[k].w * w3;
            sn = warp_sum(sn);
            if (lane == 0) atomicAdd(&g_negacc[brow * NK + k], sn);
        }

        if (r < 15) {
            wv_c = wv_n; tv_c = tv_n;
            #pragma unroll
            for (int k = 0; k < NK; k++) tn_c[k] = tn_n[k];
        }
    }

    // ---- last-CTA finalize ----
    __syncthreads();
    __shared__ int is_last;
    if (tid == 0) {
        __threadfence();
        int old = atomicAdd(&g_ctr, 1);
        is_last = (old == (int)(gridDim.x * gridDim.y) - 1) ? 1 : 0;
    }
    __syncthreads();
    if (is_last) {
        __threadfence();
        float v = 0.0f;
        #pragma unroll
        for (int j = 0; j < 4; j++) {
            int b = tid * 4 + j;
            float l = logsig(__ldcg(&g_pos[b]));
            #pragma unroll
            for (int k = 0; k < NK; k++)
                l += logsig(-__ldcg(&g_negacc[b * NK + k]));
            v += -l;
        }
        v = warp_sum(v);
        __shared__ float red[8];
        if (lane == 0) red[wid] = v;
        __syncthreads();
        if (tid == 0) {
            float sum = 0.0f;
            #pragma unroll
            for (int i = 0; i < 8; i++) sum += red[i];
            out[0] = sum * (1.0f / (float)NB);
            g_ctr = 0;
        }
    }
}

// ---------------- launch -----------------------------------------------------
extern "C" void kernel_launch(void* const* d_in, const int* in_sizes, int n_in,
                              void* d_out, int out_size)
{
    const float* vi  = (const float*)d_in[0];
    const float* vo  = (const float*)d_in[1];
    const float* neg = (const float*)d_in[2];
    const float* Vm  = (const float*)d_in[3];
    const float* U   = (const float*)d_in[4];
    float* out = (float*)d_out;

    cudaFuncSetAttribute(gemm1_kernel, cudaFuncAttributeMaxDynamicSharedMemorySize, SMEM1);
    cudaFuncSetAttribute(gemm2_kernel, cudaFuncAttributeMaxDynamicSharedMemorySize, SMEM2);

    prep_kernel<<<5000, 256>>>(Vm, U);
    gemm1_kernel<<<dim3(8, NSPLIT), 256, SMEM1>>>(vi);
    reduce_kernel<<<128, 256>>>();
    gemm2_kernel<<<dim3(8, 250), 256, SMEM2>>>(vo, neg, out);
}

// round 16
// speedup vs baseline: 2.3941x; 1.1073x over previous
#include <cuda_runtime.h>
#include <cstdint>

#define NB     1024
#define NK     5
#define NV     32000
#define ND     128
#define NSPLIT 50

// ---------------- scratch (device globals; no allocation allowed) ----------
__device__ uint32_t g_Vt[ND * (NV / 2)];        // V^T bf16x2 [d][v-word]   8.2 MB
__device__ uint32_t g_Ub[NV * (ND / 2)];        // U   bf16x2 [v][d-word]   8.2 MB
__device__ float    g_part[NSPLIT * NB * ND];   // split-K partials        26.2 MB
__device__ uint32_t g_vi_bf16[NB * (ND / 2)];   // packed vi_embed         256 KB
__device__ uint32_t g_w[NB * (NV / 2)];         // w bf16x2 [b][v-word]    65.5 MB
__device__ float    g_pos[NB];
__device__ float    g_negacc[NB * NK];
__device__ int      g_ctr;

// ---------------- helpers ----------------------------------------------------
static __device__ __forceinline__ uint32_t pack_bf16x2(float lo, float hi) {
    uint32_t r;
    asm("cvt.rn.bf16x2.f32 %0, %1, %2;" : "=r"(r) : "f"(hi), "f"(lo));
    return r;
}
static __device__ __forceinline__ float bf_lo(uint32_t w) { return __uint_as_float(w << 16); }
static __device__ __forceinline__ float bf_hi(uint32_t w) { return __uint_as_float(w & 0xFFFF0000u); }

static __device__ __forceinline__ void mma_bf16(
    float c[4], uint32_t a0, uint32_t a1, uint32_t a2, uint32_t a3,
    uint32_t b0, uint32_t b1)
{
    asm volatile(
        "mma.sync.aligned.m16n8k16.row.col.f32.bf16.bf16.f32 "
        "{%0,%1,%2,%3}, {%4,%5,%6,%7}, {%8,%9}, {%0,%1,%2,%3};"
        : "+f"(c[0]), "+f"(c[1]), "+f"(c[2]), "+f"(c[3])
        : "r"(a0), "r"(a1), "r"(a2), "r"(a3), "r"(b0), "r"(b1));
}

static __device__ __forceinline__ float logsig(float x) {
    float z = -fabsf(x);
    float l = log1pf(__expf(z));
    return (x >= 0.0f) ? -l : (x - l);
}

static __device__ __forceinline__ float warp_sum(float v) {
    #pragma unroll
    for (int o = 16; o > 0; o >>= 1) v += __shfl_xor_sync(0xFFFFFFFFu, v, o);
    return v;
}

// ---------------- kernel P: prep (V^T->bf16, U->bf16, zero accumulators) ----
__global__ void __launch_bounds__(256)
prep_kernel(const float* __restrict__ Vm, const float* __restrict__ U)
{
    const int blk = blockIdx.x;
    const int tid = threadIdx.x;

    if (blk < 4000) {
        __shared__ float sm[32][33];
        const int v0 = (blk % 1000) * 32;
        const int d0 = (blk / 1000) * 32;
        #pragma unroll
        for (int p = 0; p < 4; p++) {
            int i = (tid >> 5) + p * 8;
            int j = tid & 31;
            sm[i][j] = Vm[(size_t)(v0 + i) * ND + d0 + j];
        }
        __syncthreads();
        #pragma unroll
        for (int o = 0; o < 2; o++) {
            int row = (tid >> 4) + o * 16;
            int w   = tid & 15;
            uint32_t val = pack_bf16x2(sm[2 * w][row], sm[2 * w + 1][row]);
            g_Vt[(size_t)(d0 + row) * (NV / 2) + (v0 >> 1) + w] = val;
        }
    } else {
        int i0 = (blk - 4000) * 256 + tid;
        #pragma unroll
        for (int p = 0; p < 4; p++) {
            int i = i0 + p * 256000;
            float4 f = ((const float4*)U)[i];
            uint2 o;
            o.x = pack_bf16x2(f.x, f.y);
            o.y = pack_bf16x2(f.z, f.w);
            ((uint2*)g_Ub)[i] = o;
        }
        if (blk == 4000) {
            for (int i = tid; i < NB; i += 256)      g_pos[i] = 0.0f;
            for (int i = tid; i < NB * NK; i += 256) g_negacc[i] = 0.0f;
        }
    }
}

// ---------------- kernel 1: partials of vi @ V  (bf16, split-K, pipelined) --
#define G1S 36
static constexpr int SMEM1 = 2 * 2 * 128 * G1S * 4;   // 73728 B

__global__ void __launch_bounds__(256, 1)
gemm1_kernel(const float* __restrict__ vi)
{
    extern __shared__ uint32_t sm1[];
    const int tid  = threadIdx.x;
    const int wid  = tid >> 5;
    const int lane = tid & 31;
    const int g    = lane >> 2;
    const int tig  = lane & 3;
    const int m0   = blockIdx.x * 128;
    const int wrow = wid * 16;
    const int split = blockIdx.y;
    const size_t kbase = (size_t)split * 640;

    float acc[16][4];
    #pragma unroll
    for (int nt = 0; nt < 16; nt++)
        #pragma unroll
        for (int j = 0; j < 4; j++) acc[nt][j] = 0.0f;

    float4 ra[8];
    uint4  rbv[4];
    const int ar = tid >> 4, ac4 = tid & 15;
    const int brr = tid >> 3, bw4 = tid & 7;

    #define G1_LDG(IT)                                                            \
        do {                                                                      \
            size_t k0 = kbase + (size_t)(IT) * 64;                                \
            _Pragma("unroll")                                                     \
            for (int t = 0; t < 8; t++)                                           \
                ra[t] = *(const float4*)(vi + (size_t)(m0 + ar + t * 16) * NV + k0 + ac4 * 4); \
            _Pragma("unroll")                                                     \
            for (int t = 0; t < 4; t++)                                           \
                rbv[t] = *(const uint4*)(g_Vt + (size_t)(brr + t * 32) * (NV / 2) + (k0 >> 1) + bw4 * 4); \
        } while (0)

    #define G1_STS(P)                                                             \
        do {                                                                      \
            uint32_t* Aw = sm1 + (P) * (2 * 128 * G1S);                           \
            uint32_t* Bw = Aw + 128 * G1S;                                        \
            _Pragma("unroll")                                                     \
            for (int t = 0; t < 8; t++) {                                         \
                uint2 p;                                                          \
                p.x = pack_bf16x2(ra[t].x, ra[t].y);                              \
                p.y = pack_bf16x2(ra[t].z, ra[t].w);                              \
                *(uint2*)(Aw + (ar + t * 16) * G1S + ac4 * 2) = p;                \
            }                                                                     \
            _Pragma("unroll")                                                     \
            for (int t = 0; t < 4; t++)                                           \
                *(uint4*)(Bw + (brr + t * 32) * G1S + bw4 * 4) = rbv[t];          \
        } while (0)

    G1_LDG(0);
    G1_STS(0);
    __syncthreads();

    for (int it = 0; it < 10; it++) {
        if (it + 1 < 10) G1_LDG(it + 1);

        const uint32_t* Aw = sm1 + (it & 1) * (2 * 128 * G1S);
        const uint32_t* Bw = Aw + 128 * G1S;

        #pragma unroll
        for (int ks = 0; ks < 4; ks++) {
            const int kw = ks * 8;
            uint32_t a0 = Aw[(wrow + g)     * G1S + kw + tig];
            uint32_t a1 = Aw[(wrow + g + 8) * G1S + kw + tig];
            uint32_t a2 = Aw[(wrow + g)     * G1S + kw + tig + 4];
            uint32_t a3 = Aw[(wrow + g + 8) * G1S + kw + tig + 4];
            #pragma unroll
            for (int nt = 0; nt < 16; nt++) {
                uint32_t b0 = Bw[(nt * 8 + g) * G1S + kw + tig];
                uint32_t b1 = Bw[(nt * 8 + g) * G1S + kw + tig + 4];
                mma_bf16(acc[nt], a0, a1, a2, a3, b0, b1);
            }
        }

        if (it + 1 < 10) {
            G1_STS(1 - (it & 1));
            __syncthreads();
        }
    }

    float* dst0 = g_part + ((size_t)split * NB + (m0 + wrow + g)) * ND + 2 * tig;
    float* dst1 = dst0 + 8 * ND;
    #pragma unroll
    for (int nt = 0; nt < 16; nt++) {
        *(float2*)(dst0 + nt * 8) = make_float2(acc[nt][0], acc[nt][1]);
        *(float2*)(dst1 + nt * 8) = make_float2(acc[nt][2], acc[nt][3]);
    }
}

// ---------------- kernel R: reduce partials -> packed bf16 vi_embed ---------
__global__ void __launch_bounds__(256)
reduce_kernel()
{
    int e4 = blockIdx.x * 256 + threadIdx.x;
    float4 a = make_float4(0.f, 0.f, 0.f, 0.f);
    #pragma unroll 10
    for (int s = 0; s < NSPLIT; s++) {
        float4 f = *(const float4*)(g_part + (size_t)s * (NB * ND) + (size_t)e4 * 4);
        a.x += f.x; a.y += f.y; a.z += f.z; a.w += f.w;
    }
    uint2 o;
    o.x = pack_bf16x2(a.x, a.y);
    o.y = pack_bf16x2(a.z, a.w);
    ((uint2*)g_vi_bf16)[e4] = o;
}

// ---------------- kernel 2a: wgen — w = vi_embed @ U^T -> gmem bf16 ---------
// grid (8 m-tiles, 250 v-tiles). Per-warp MMA over its 16-row strip; w tile
// staged in smem then written coalesced to g_w[b][v].
#define BSW 68
#define WSW 66
static constexpr int SMEM2 = 128 * BSW * 4 + 128 * WSW * 4;   // 68608 B

__global__ void __launch_bounds__(256, 3)
wgen_kernel()
{
    extern __shared__ uint32_t sm2[];
    uint32_t* Bs = sm2;               // [128][BSW] bf16x2: U tile (row=v)
    uint32_t* Ws = sm2 + 128 * BSW;   // [128][WSW] bf16x2: w tile (row=b)

    const int tid  = threadIdx.x;
    const int wid  = tid >> 5;
    const int lane = tid & 31;
    const int g    = lane >> 2;
    const int tig  = lane & 3;
    const int m0   = blockIdx.x * 128;
    const int v0   = blockIdx.y * 128;
    const int wrow = wid * 16;

    #pragma unroll
    for (int t = 0; t < 16; t++) {
        int r = wid + t * 8;
        uint2 w2 = *(const uint2*)(g_Ub + (size_t)(v0 + r) * (ND / 2) + lane * 2);
        *(uint2*)(Bs + r * BSW + lane * 2) = w2;
    }

    uint32_t af[8][4];
    {
        const uint32_t* ap = g_vi_bf16 + (size_t)(m0 + wrow + g) * (ND / 2);
        #pragma unroll
        for (int ks = 0; ks < 8; ks++) {
            af[ks][0] = ap[ks * 8 + tig];
            af[ks][1] = ap[8 * (ND / 2) + ks * 8 + tig];
            af[ks][2] = ap[ks * 8 + tig + 4];
            af[ks][3] = ap[8 * (ND / 2) + ks * 8 + tig + 4];
        }
    }
    __syncthreads();

    const int rA = wrow + g;
    const int rB = rA + 8;
    #pragma unroll
    for (int nt = 0; nt < 16; nt++) {
        float a4[4] = {0.0f, 0.0f, 0.0f, 0.0f};
        #pragma unroll
        for (int ks = 0; ks < 8; ks++) {
            uint32_t b0 = Bs[(nt * 8 + g) * BSW + ks * 8 + tig];
            uint32_t b1 = Bs[(nt * 8 + g) * BSW + ks * 8 + tig + 4];
            mma_bf16(a4, af[ks][0], af[ks][1], af[ks][2], af[ks][3], b0, b1);
        }
        Ws[rA * WSW + nt * 4 + tig] = pack_bf16x2(a4[0], a4[1]);
        Ws[rB * WSW + nt * 4 + tig] = pack_bf16x2(a4[2], a4[3]);
    }
    __syncwarp();

    // coalesced store of this warp's 16 w rows (256 B per row)
    const int vw0 = v0 >> 1;
    #pragma unroll
    for (int r = 0; r < 16; r++) {
        const int rt = wrow + r;
        uint2 wv = *(const uint2*)(Ws + rt * WSW + lane * 2);
        *(uint2*)(g_w + (size_t)(m0 + rt) * (NV / 2) + vw0 + lane * 2) = wv;
    }
}

// ---------------- kernel 2b: pure stream — dot(vo,w), dot(neg_k,w) ----------
// grid (2 col-halves, 1024 b). Warp processes 128-col iters strided by 8.
// 7 independent LDGs per iter, reductions deferred to one shfl pass per warp.
__global__ void __launch_bounds__(256, 4)
stream_kernel(const float* __restrict__ vo, const float* __restrict__ neg,
              float* __restrict__ out)
{
    const int tid  = threadIdx.x;
    const int wid  = tid >> 5;
    const int lane = tid & 31;
    const int b    = blockIdx.y;
    const int h    = blockIdx.x;

    const float*    vp = vo + (size_t)b * NV;
    const float*    np = neg + (size_t)b * (NK * NV);
    const uint32_t* wp = g_w + (size_t)b * (NV / 2);

    float s[6] = {0.f, 0.f, 0.f, 0.f, 0.f, 0.f};

    const int iend = h * 125 + 125;
    #pragma unroll 2
    for (int i = h * 125 + wid; i < iend; i += 8) {
        const int c = i * 128 + lane * 4;

        uint2  wv = __ldcs((const uint2*)(wp + (c >> 1)));
        float4 tv = __ldcs((const float4*)(vp + c));
        float4 u0 = __ldcs((const float4*)(np + 0 * NV + c));
        float4 u1 = __ldcs((const float4*)(np + 1 * NV + c));
        float4 u2 = __ldcs((const float4*)(np + 2 * NV + c));
        float4 u3 = __ldcs((const float4*)(np + 3 * NV + c));
        float4 u4 = __ldcs((const float4*)(np + 4 * NV + c));

        const float w0 = bf_lo(wv.x), w1 = bf_hi(wv.x);
        const float w2 = bf_lo(wv.y), w3 = bf_hi(wv.y);

        s[0] += tv.x * w0 + tv.y * w1 + tv.z * w2 + tv.w * w3;
        s[1] += u0.x * w0 + u0.y * w1 + u0.z * w2 + u0.w * w3;
        s[2] += u1.x * w0 + u1.y * w1 + u1.z * w2 + u1.w * w3;
        s[3] += u2.x * w0 + u2.y * w1 + u2.z * w2 + u2.w * w3;
        s[4] += u3.x * w0 + u3.y * w1 + u3.z * w2 + u3.w * w3;
        s[5] += u4.x * w0 + u4.y * w1 + u4.z * w2 + u4.w * w3;
    }

    #pragma unroll
    for (int i = 0; i < 6; i++) s[i] = warp_sum(s[i]);
    if (lane == 0) {
        atomicAdd(&g_pos[b], s[0]);
        #pragma unroll
        for (int k = 0; k < NK; k++)
            atomicAdd(&g_negacc[b * NK + k], s[k + 1]);
    }

    // ---- last-CTA finalize ----
    __syncthreads();
    __shared__ int is_last;
    if (tid == 0) {
        __threadfence();
        int old = atomicAdd(&g_ctr, 1);
        is_last = (old == (int)(gridDim.x * gridDim.y) - 1) ? 1 : 0;
    }
    __syncthreads();
    if (is_last) {
        __threadfence();
        float v = 0.0f;
        #pragma unroll
        for (int j = 0; j < 4; j++) {
            int bb = tid * 4 + j;
            float l = logsig(__ldcg(&g_pos[bb]));
            #pragma unroll
            for (int k = 0; k < NK; k++)
                l += logsig(-__ldcg(&g_negacc[bb * NK + k]));
            v += -l;
        }
        v = warp_sum(v);
        __shared__ float red[8];
        if (lane == 0) red[wid] = v;
        __syncthreads();
        if (tid == 0) {
            float sum = 0.0f;
            #pragma unroll
            for (int i = 0; i < 8; i++) sum += red[i];
            out[0] = sum * (1.0f / (float)NB);
            g_ctr = 0;
        }
    }
}

// ---------------- launch -----------------------------------------------------
extern "C" void kernel_launch(void* const* d_in, const int* in_sizes, int n_in,
                              void* d_out, int out_size)
{
    const float* vi  = (const float*)d_in[0];
    const float* vo  = (const float*)d_in[1];
    const float* neg = (const float*)d_in[2];
    const float* Vm  = (const float*)d_in[3];
    const float* U   = (const float*)d_in[4];
    float* out = (float*)d_out;

    cudaFuncSetAttribute(gemm1_kernel, cudaFuncAttributeMaxDynamicSharedMemorySize, SMEM1);
    cudaFuncSetAttribute(wgen_kernel,  cudaFuncAttributeMaxDynamicSharedMemorySize, SMEM2);

    prep_kernel<<<5000, 256>>>(Vm, U);
    gemm1_kernel<<<dim3(8, NSPLIT), 256, SMEM1>>>(vi);
    reduce_kernel<<<128, 256>>>();
    wgen_kernel<<<dim3(8, 250), 256, SMEM2>>>();
    stream_kernel<<<dim3(2, NB), 256>>>(vo, neg, out);
}